// round 3
// baseline (speedup 1.0000x reference)
#include <cuda_runtime.h>
#include <math.h>
#include <stdint.h>

typedef unsigned long long u64;

#define NB   64
#define HID  512
#define VOC  32000
#define TT   50
#define NBLK_B 250
#define START_TOK 1
#define END_TOK 2

// ---------------- device scratch (no allocations allowed) ----------------
__device__ float g_h[NB * HID];
__device__ float g_c[NB * HID];
__device__ float g_gp[4][NB * 2048];      // split-K gate partials
__device__ int   g_word[NB];
__device__ int   g_mask[NB];
__device__ int   g_done;
__device__ float g_pv[NBLK_B * NB];       // per-block argmax partial values
__device__ int   g_pi[NBLK_B * NB];       // per-block argmax partial indices

// ---------------- f32x2 helpers ----------------
__device__ __forceinline__ u64 pack2(float a, float b) {
    u64 r; asm("mov.b64 %0, {%1, %2};" : "=l"(r) : "f"(a), "f"(b)); return r;
}
__device__ __forceinline__ void unpack2(u64 v, float &a, float &b) {
    asm("mov.b64 {%0, %1}, %2;" : "=f"(a), "=f"(b) : "l"(v));
}
__device__ __forceinline__ void ffma2(u64 &d, u64 a, u64 b) {
    asm("fma.rn.f32x2 %0, %1, %2, %0;" : "+l"(d) : "l"(a), "l"(b));
}
__device__ __forceinline__ float f4get(const float4 &v, int k) {
    return k == 0 ? v.x : k == 1 ? v.y : k == 2 ? v.z : v.w;
}

// ---------------- init ----------------
__global__ void kInit(const float* __restrict__ feat) {
    int i = blockIdx.x * blockDim.x + threadIdx.x;
    if (i < NB * HID) { g_h[i] = feat[i]; g_c[i] = 0.f; }
    if (i < NB)       { g_word[i] = START_TOK; g_mask[i] = 0; }
    if (i == 0)         g_done = 0;
}

// ---------------- kGates: split-K gates GEMM --------------------------
// grid (16, 4): x -> 128 gate rows, y = k-slice of 256.
// slices 0,1: x = emb[word] vs W_ih; slices 2,3: h vs W_hh.
__global__ __launch_bounds__(256) void kGates(const float* __restrict__ emb,
                                              const float* __restrict__ Wih,
                                              const float* __restrict__ Whh) {
    if (g_done) return;
    __shared__ __align__(16) float sh[128 * 66];
    const int tid = threadIdx.x, rg = tid >> 3, bg = tid & 7;
    const int ks = blockIdx.y;
    const int j0 = blockIdx.x * 128;
    const int r0 = j0 + 4 * rg;
    const int b0 = 8 * bg;
    const float* W  = (ks < 2) ? Wih : Whh;
    const int koff  = 256 * (ks & 1);

    const float4* wp[4];
    #pragma unroll
    for (int r = 0; r < 4; r++)
        wp[r] = reinterpret_cast<const float4*>(W + (size_t)(r0 + r) * 512 + koff);

    u64 acc[16];
    #pragma unroll
    for (int i = 0; i < 16; i++) acc[i] = 0ull;

    for (int ch = 0; ch < 2; ch++) {
        for (int idx = tid; idx < 64 * 128; idx += 256) {
            int b = idx >> 7, k = idx & 127;
            float v;
            if (ks < 2)
                v = emb[(size_t)g_word[b] * 512 + koff + 128 * ch + k];
            else
                v = g_h[b * 512 + koff + 128 * ch + k];
            sh[k * 66 + b] = v;
        }
        __syncthreads();
        #pragma unroll 4
        for (int k4 = 0; k4 < 32; k4++) {
            float4 wv[4];
            #pragma unroll
            for (int r = 0; r < 4; r++) wv[r] = wp[r][32 * ch + k4];
            #pragma unroll
            for (int kk = 0; kk < 4; kk++) {
                u64 h2[4];
                #pragma unroll
                for (int p = 0; p < 4; p++)
                    h2[p] = *reinterpret_cast<const u64*>(&sh[(4 * k4 + kk) * 66 + b0 + 2 * p]);
                #pragma unroll
                for (int r = 0; r < 4; r++) {
                    float w = f4get(wv[r], kk);
                    u64 wd = pack2(w, w);
                    #pragma unroll
                    for (int p = 0; p < 4; p++) ffma2(acc[r * 4 + p], wd, h2[p]);
                }
            }
        }
        __syncthreads();
    }
    // transpose partials through smem, store coalesced
    #pragma unroll
    for (int r = 0; r < 4; r++)
        #pragma unroll
        for (int p = 0; p < 4; p++) {
            float a, b; unpack2(acc[r * 4 + p], a, b);
            sh[(4 * rg + r) * 66 + b0 + 2 * p]     = a;
            sh[(4 * rg + r) * 66 + b0 + 2 * p + 1] = b;
        }
    __syncthreads();
    float* dst = g_gp[ks];
    for (int idx = tid; idx < 8192; idx += 256) {
        int b = idx >> 7, rl = idx & 127;
        dst[b * 2048 + j0 + rl] = sh[rl * 66 + b];
    }
}

// ---------------- kPoint: sum split-K partials + bias + LSTM pointwise ----
__global__ void kPoint(const float* __restrict__ bih, const float* __restrict__ bhh) {
    if (g_done) return;
    int gid = blockIdx.x * blockDim.x + threadIdx.x;   // 64 blocks * 512 = 32768
    int b = gid >> 9, u = gid & 511;
    float gate[4];
    #pragma unroll
    for (int q = 0; q < 4; q++) {
        int j = u + 512 * q;
        float s = bih[j] + bhh[j];
        #pragma unroll
        for (int ks = 0; ks < 4; ks++) s += g_gp[ks][b * 2048 + j];
        gate[q] = s;
    }
    float ii = 1.f / (1.f + expf(-gate[0]));
    float ff = 1.f / (1.f + expf(-gate[1]));
    float gg = tanhf(gate[2]);
    float oo = 1.f / (1.f + expf(-gate[3]));
    float c = ff * g_c[gid] + ii * gg;
    g_c[gid] = c;
    g_h[gid] = oo * tanhf(c);
}

// ---------------- kB: logits GEMM + bias + block argmax + output store ----
// grid 250: block owns 128 vocab rows x 64 batches.
__global__ __launch_bounds__(256) void kB(const float* __restrict__ Wl,
                                          const float* __restrict__ bl,
                                          float* __restrict__ out, int t) {
    __shared__ __align__(16) float sh[128 * 66];
    __shared__ float cv[4 * 64];
    __shared__ int   ci[4 * 64];
    const int tid = threadIdx.x, rg = tid >> 3, bg = tid & 7;
    const int blk = blockIdx.x;
    const int r0 = blk * 128 + 4 * rg;
    const int b0 = 8 * bg;

    if (g_done) {   // sequence already finished: reference emits zeros
        for (int idx = tid; idx < 8192; idx += 256) {
            int b = idx >> 7, rl = idx & 127;
            out[(size_t)b * (TT * VOC) + (size_t)t * VOC + blk * 128 + rl] = 0.f;
        }
        return;
    }

    const float4* wp[4];
    #pragma unroll
    for (int r = 0; r < 4; r++)
        wp[r] = reinterpret_cast<const float4*>(Wl + (size_t)(r0 + r) * 512);

    u64 acc[16];
    #pragma unroll
    for (int i = 0; i < 16; i++) acc[i] = 0ull;

    for (int ch = 0; ch < 4; ch++) {
        for (int idx = tid; idx < 64 * 128; idx += 256) {
            int b = idx >> 7, k = idx & 127;
            sh[k * 66 + b] = g_h[b * 512 + 128 * ch + k];
        }
        __syncthreads();
        #pragma unroll 4
        for (int k4 = 0; k4 < 32; k4++) {
            float4 wv[4];
            #pragma unroll
            for (int r = 0; r < 4; r++) wv[r] = wp[r][32 * ch + k4];
            #pragma unroll
            for (int kk = 0; kk < 4; kk++) {
                u64 h2[4];
                #pragma unroll
                for (int p = 0; p < 4; p++)
                    h2[p] = *reinterpret_cast<const u64*>(&sh[(4 * k4 + kk) * 66 + b0 + 2 * p]);
                #pragma unroll
                for (int r = 0; r < 4; r++) {
                    float w = f4get(wv[r], kk);
                    u64 wd = pack2(w, w);
                    #pragma unroll
                    for (int p = 0; p < 4; p++) ffma2(acc[r * 4 + p], wd, h2[p]);
                }
            }
        }
        __syncthreads();
    }

    // add bias, write logits tile transposed into smem
    #pragma unroll
    for (int r = 0; r < 4; r++) {
        float bv = bl[r0 + r];
        #pragma unroll
        for (int p = 0; p < 4; p++) {
            float a, b; unpack2(acc[r * 4 + p], a, b);
            sh[(4 * rg + r) * 66 + b0 + 2 * p]     = a + bv;
            sh[(4 * rg + r) * 66 + b0 + 2 * p + 1] = b + bv;
        }
    }
    __syncthreads();

    // per-block argmax partial (first-index tie-break: ascending, strict >)
    {
        int b = tid & 63, q = tid >> 6;       // quarter q owns rows [32q, 32q+32)
        float best = -1e30f; int bidx = 0;
        for (int rl = 32 * q; rl < 32 * q + 32; rl++) {
            float v = sh[rl * 66 + b];
            if (v > best) { best = v; bidx = blk * 128 + rl; }
        }
        cv[q * 64 + b] = best; ci[q * 64 + b] = bidx;
    }
    __syncthreads();
    if (tid < 64) {
        int b = tid;
        float best = cv[b]; int bidx = ci[b];
        #pragma unroll
        for (int q = 1; q < 4; q++) {
            float v = cv[q * 64 + b];
            if (v > best) { best = v; bidx = ci[q * 64 + b]; }
        }
        g_pv[blk * 64 + b] = best; g_pi[blk * 64 + b] = bidx;
    }

    // coalesced logits store
    for (int idx = tid; idx < 8192; idx += 256) {
        int b = idx >> 7, rl = idx & 127;
        out[(size_t)b * (TT * VOC) + (size_t)t * VOC + blk * 128 + rl] = sh[rl * 66 + b];
    }
}

// ---------------- kC: argmax finalize, word/mask/done update ----------------
__global__ void kC() {
    if (g_done) return;
    __shared__ float sv[64 * 4];
    __shared__ int   si[64 * 4];
    __shared__ int   sm[64];
    int tid = threadIdx.x;
    int b = tid >> 2, q = tid & 3;
    int s = q * 63, e = (s + 63 < NBLK_B) ? s + 63 : NBLK_B;
    float best = -1e30f; int bidx = 0;
    for (int k = s; k < e; k++) {
        float v = g_pv[k * 64 + b];
        if (v > best) { best = v; bidx = g_pi[k * 64 + b]; }
    }
    sv[b * 4 + q] = best; si[b * 4 + q] = bidx;
    __syncthreads();
    if (tid < 64) {
        int bb = tid;
        float bv = sv[bb * 4]; int bi = si[bb * 4];
        #pragma unroll
        for (int q2 = 1; q2 < 4; q2++) {
            if (sv[bb * 4 + q2] > bv) { bv = sv[bb * 4 + q2]; bi = si[bb * 4 + q2]; }
        }
        g_word[bb] = bi;
        int m = g_mask[bb] | (bi == END_TOK);
        g_mask[bb] = m;
        sm[bb] = m;
    }
    __syncthreads();
    if (tid == 0) {
        int all = 1;
        for (int b2 = 0; b2 < 64; b2++) all &= sm[b2];
        if (all) g_done = 1;
    }
}

extern "C" void kernel_launch(void* const* d_in, const int* in_sizes, int n_in,
                              void* d_out, int out_size) {
    const float* feat = (const float*)d_in[0];
    const float* emb  = (const float*)d_in[1];
    const float* Wih  = (const float*)d_in[2];
    const float* Whh  = (const float*)d_in[3];
    const float* bih  = (const float*)d_in[4];
    const float* bhh  = (const float*)d_in[5];
    const float* Wl   = (const float*)d_in[6];
    const float* bl   = (const float*)d_in[7];
    float* out = (float*)d_out;

    kInit<<<128, 256>>>(feat);
    for (int t = 0; t < TT; t++) {
        kGates<<<dim3(16, 4), 256>>>(emb, Wih, Whh);
        kPoint<<<64, 512>>>(bih, bhh);
        kB<<<250, 256>>>(Wl, bl, out, t);
        kC<<<1, 256>>>();
    }
}

// round 4
// speedup vs baseline: 1.2099x; 1.2099x over previous
#include <cuda_runtime.h>
#include <math.h>
#include <stdint.h>

typedef unsigned long long u64;

#define NB   64
#define HID  512
#define VOC  32000
#define TT   50
#define NBLK_B 125
#define NKS  16
#define START_TOK 1
#define END_TOK 2

// ---------------- device scratch ----------------
__device__ float g_Wlt[HID * VOC];        // W_lin transposed [k][r]
__device__ float g_Wgt[1024 * 2048];      // gates W transposed [k][j] (k<512: Wih, k>=512: Whh)
__device__ float g_sv[1024 * NB];         // source vec transposed [k][b]; [512..1024) = h
__device__ float g_c[NB * HID];
__device__ float g_gp[NKS][NB * 2048];    // split-K gate partials
__device__ int   g_word[NB];
__device__ int   g_mask[NB];
__device__ int   g_done;
__device__ float g_pv[NBLK_B * NB];
__device__ int   g_pi[NBLK_B * NB];

// ---------------- f32x2 helpers ----------------
__device__ __forceinline__ u64 pack2(float a, float b) {
    u64 r; asm("mov.b64 %0, {%1, %2};" : "=l"(r) : "f"(a), "f"(b)); return r;
}
__device__ __forceinline__ void unpack2(u64 v, float &a, float &b) {
    asm("mov.b64 {%0, %1}, %2;" : "=f"(a), "=f"(b) : "l"(v));
}
__device__ __forceinline__ void ffma2(u64 &d, u64 a, u64 b) {
    asm("fma.rn.f32x2 %0, %1, %2, %0;" : "+l"(d) : "l"(a), "l"(b));
}

// ---------------- weight transposes (run once per replay) ----------------
__global__ void kTransL(const float* __restrict__ Wl) {
    __shared__ float tile[32][33];
    int r0 = blockIdx.x * 32, k0 = blockIdx.y * 32;
    int tx = threadIdx.x, ty = threadIdx.y;
    #pragma unroll
    for (int i = 0; i < 4; i++)
        tile[ty + 8 * i][tx] = Wl[(size_t)(r0 + ty + 8 * i) * HID + k0 + tx];
    __syncthreads();
    #pragma unroll
    for (int i = 0; i < 4; i++)
        g_Wlt[(size_t)(k0 + ty + 8 * i) * VOC + r0 + tx] = tile[tx][ty + 8 * i];
}

__global__ void kTransG(const float* __restrict__ Wih, const float* __restrict__ Whh) {
    __shared__ float tile[32][33];
    int j0 = blockIdx.x * 32, k0 = blockIdx.y * 32;
    const float* W = (k0 < 512) ? Wih : Whh;
    int kk = (k0 < 512) ? k0 : k0 - 512;
    int tx = threadIdx.x, ty = threadIdx.y;
    #pragma unroll
    for (int i = 0; i < 4; i++)
        tile[ty + 8 * i][tx] = W[(size_t)(j0 + ty + 8 * i) * 512 + kk + tx];
    __syncthreads();
    #pragma unroll
    for (int i = 0; i < 4; i++)
        g_Wgt[(size_t)(k0 + ty + 8 * i) * 2048 + j0 + tx] = tile[tx][ty + 8 * i];
}

// ---------------- init ----------------
__global__ void kInit(const float* __restrict__ feat) {
    int gid = blockIdx.x * blockDim.x + threadIdx.x;    // 32768
    if (gid < NB * HID) {
        int b = gid >> 9, u = gid & 511;
        g_c[gid] = 0.f;
        g_sv[(512 + u) * 64 + b] = feat[gid];
    }
    if (gid < NB) { g_word[gid] = START_TOK; g_mask[gid] = 0; }
    if (gid == 0)   g_done = 0;
}

// ---------------- FMA micro-step: 8 rows x 4 batch-pairs ----------------
__device__ __forceinline__ void mstep(u64 (&acc)[8][4], float4 w0, float4 w1,
                                      const u64 (&h)[4]) {
    u64 wd[8];
    wd[0] = pack2(w0.x, w0.x); wd[1] = pack2(w0.y, w0.y);
    wd[2] = pack2(w0.z, w0.z); wd[3] = pack2(w0.w, w0.w);
    wd[4] = pack2(w1.x, w1.x); wd[5] = pack2(w1.y, w1.y);
    wd[6] = pack2(w1.z, w1.z); wd[7] = pack2(w1.w, w1.w);
    #pragma unroll
    for (int r = 0; r < 8; r++)
        #pragma unroll
        for (int p = 0; p < 4; p++)
            ffma2(acc[r][p], wd[r], h[p]);
}

// ---------------- kGates: split-K gates GEMM --------------------------
// grid (8, 16): x -> 256 gate rows, y = k-slice of 64 (k<512: x=emb[word], else h).
__global__ __launch_bounds__(256) void kGates(const float* __restrict__ emb) {
    if (g_done) return;
    const int tid = threadIdx.x, lane = tid & 31, wid = tid >> 5;
    const int ks = blockIdx.y;
    const int r0 = blockIdx.x * 256 + lane * 8;
    const int b0 = wid * 8;
    const int kb = ks * 64;

    u64 acc[8][4];
    #pragma unroll
    for (int r = 0; r < 8; r++)
        #pragma unroll
        for (int p = 0; p < 4; p++) acc[r][p] = 0ull;

    const float4* wp = reinterpret_cast<const float4*>(g_Wgt + (size_t)kb * 2048 + r0);

    if (ks < 8) {
        const float* xr[8];
        #pragma unroll
        for (int j = 0; j < 8; j++)
            xr[j] = emb + (size_t)g_word[b0 + j] * 512 + kb;
        for (int k = 0; k < 64; k++) {
            float4 w0 = wp[0], w1 = wp[1]; wp += 512;
            u64 h2[4];
            #pragma unroll
            for (int p = 0; p < 4; p++)
                h2[p] = pack2(xr[2 * p][k], xr[2 * p + 1][k]);
            mstep(acc, w0, w1, h2);
        }
    } else {
        const u64* hp = reinterpret_cast<const u64*>(g_sv + (size_t)kb * 64 + b0);
        for (int k = 0; k < 64; k++) {
            float4 w0 = wp[0], w1 = wp[1]; wp += 512;
            u64 h2[4];
            #pragma unroll
            for (int p = 0; p < 4; p++) h2[p] = hp[p];
            hp += 32;
            mstep(acc, w0, w1, h2);
        }
    }
    // store partials: for each batch pair, 2 batches x 8 rows
    #pragma unroll
    for (int p = 0; p < 4; p++) {
        float va[8], vb[8];
        #pragma unroll
        for (int r = 0; r < 8; r++) unpack2(acc[r][p], va[r], vb[r]);
        float* da = &g_gp[ks][(b0 + 2 * p) * 2048 + r0];
        float* db = &g_gp[ks][(b0 + 2 * p + 1) * 2048 + r0];
        *reinterpret_cast<float4*>(da)     = make_float4(va[0], va[1], va[2], va[3]);
        *reinterpret_cast<float4*>(da + 4) = make_float4(va[4], va[5], va[6], va[7]);
        *reinterpret_cast<float4*>(db)     = make_float4(vb[0], vb[1], vb[2], vb[3]);
        *reinterpret_cast<float4*>(db + 4) = make_float4(vb[4], vb[5], vb[6], vb[7]);
    }
}

// ---------------- kPoint: sum split-K partials + bias + LSTM pointwise ----
__global__ void kPoint(const float* __restrict__ bih, const float* __restrict__ bhh) {
    if (g_done) return;
    int gid = blockIdx.x * blockDim.x + threadIdx.x;   // 64 x 512
    int b = gid >> 9, u = gid & 511;
    float gate[4];
    #pragma unroll
    for (int q = 0; q < 4; q++) {
        int j = u + 512 * q;
        float s = bih[j] + bhh[j];
        #pragma unroll
        for (int ks = 0; ks < NKS; ks++) s += g_gp[ks][b * 2048 + j];
        gate[q] = s;
    }
    float ii = 1.f / (1.f + expf(-gate[0]));
    float ff = 1.f / (1.f + expf(-gate[1]));
    float gg = tanhf(gate[2]);
    float oo = 1.f / (1.f + expf(-gate[3]));
    float c = ff * g_c[gid] + ii * gg;
    g_c[gid] = c;
    g_sv[(512 + u) * 64 + b] = oo * tanhf(c);
}

// ---------------- kB: logits GEMM + bias + block argmax + output store ----
// grid 125: block owns 256 vocab rows x 64 batches. lane -> 8 rows, warp -> 8 batches.
__global__ __launch_bounds__(256) void kB(const float* __restrict__ bl,
                                          float* __restrict__ out, int t) {
    const int tid = threadIdx.x, lane = tid & 31, wid = tid >> 5;
    const int blk = blockIdx.x;
    const int r0 = blk * 256 + lane * 8;
    const int b0 = wid * 8;

    if (g_done) {
        for (int idx = tid; idx < 256 * 64; idx += 256) {
            int b = idx >> 8, r = idx & 255;
            out[(size_t)b * (TT * VOC) + (size_t)t * VOC + blk * 256 + r] = 0.f;
        }
        return;
    }

    u64 acc[8][4];
    #pragma unroll
    for (int r = 0; r < 8; r++)
        #pragma unroll
        for (int p = 0; p < 4; p++) acc[r][p] = 0ull;

    const float4* wp = reinterpret_cast<const float4*>(g_Wlt + r0);   // +8000 f4/k
    const u64* hp = reinterpret_cast<const u64*>(g_sv + 512 * 64 + b0); // +32/k

    float4 wa0 = wp[0], wa1 = wp[1], wa2 = wp[8000], wa3 = wp[8001];
    wp += 16000;

    for (int k = 0; k < 510; k += 2) {
        float4 wn0 = wp[0], wn1 = wp[1], wn2 = wp[8000], wn3 = wp[8001];
        wp += 16000;
        u64 h0[4], h1[4];
        #pragma unroll
        for (int p = 0; p < 4; p++) { h0[p] = hp[p]; h1[p] = hp[32 + p]; }
        hp += 64;
        mstep(acc, wa0, wa1, h0);
        mstep(acc, wa2, wa3, h1);
        wa0 = wn0; wa1 = wn1; wa2 = wn2; wa3 = wn3;
    }
    {   // epilogue k = 510, 511
        u64 h0[4], h1[4];
        #pragma unroll
        for (int p = 0; p < 4; p++) { h0[p] = hp[p]; h1[p] = hp[32 + p]; }
        mstep(acc, wa0, wa1, h0);
        mstep(acc, wa2, wa3, h1);
    }

    float4 bv0 = *reinterpret_cast<const float4*>(bl + r0);
    float4 bv1 = *reinterpret_cast<const float4*>(bl + r0 + 4);
    float bias[8] = {bv0.x, bv0.y, bv0.z, bv0.w, bv1.x, bv1.y, bv1.z, bv1.w};

    #pragma unroll
    for (int p = 0; p < 4; p++) {
        float va[8], vb[8];
        #pragma unroll
        for (int r = 0; r < 8; r++) {
            float a, b_; unpack2(acc[r][p], a, b_);
            va[r] = a + bias[r]; vb[r] = b_ + bias[r];
        }
        #pragma unroll
        for (int half = 0; half < 2; half++) {
            const float* v = half ? vb : va;
            int b = b0 + 2 * p + half;
            // thread-local argmax, rows ascending (first-max tie-break)
            float bestv = v[0]; int besti = r0;
            #pragma unroll
            for (int i = 1; i < 8; i++)
                if (v[i] > bestv) { bestv = v[i]; besti = r0 + i; }
            // warp reduce with lower-index tie rule
            #pragma unroll
            for (int s = 16; s > 0; s >>= 1) {
                float ov = __shfl_xor_sync(0xffffffffu, bestv, s);
                int   oi = __shfl_xor_sync(0xffffffffu, besti, s);
                if (ov > bestv || (ov == bestv && oi < besti)) { bestv = ov; besti = oi; }
            }
            if (lane == 0) { g_pv[blk * 64 + b] = bestv; g_pi[blk * 64 + b] = besti; }
            float* op = out + (size_t)b * (TT * VOC) + (size_t)t * VOC + r0;
            *reinterpret_cast<float4*>(op)     = make_float4(v[0], v[1], v[2], v[3]);
            *reinterpret_cast<float4*>(op + 4) = make_float4(v[4], v[5], v[6], v[7]);
        }
    }
}

// ---------------- kC: argmax finalize, word/mask/done update ----------------
__global__ void kC() {
    if (g_done) return;
    __shared__ float sv[256];
    __shared__ int   si[256];
    __shared__ int   sm[64];
    int tid = threadIdx.x;
    int b = tid & 63, q = tid >> 6;
    int s = q * 32, e = (s + 32 < NBLK_B) ? s + 32 : NBLK_B;
    float best = -1e30f; int bi = 0x7fffffff;
    for (int k = s; k < e; k++) {
        float v = g_pv[k * 64 + b];
        int   i = g_pi[k * 64 + b];
        if (v > best || (v == best && i < bi)) { best = v; bi = i; }
    }
    sv[q * 64 + b] = best; si[q * 64 + b] = bi;
    __syncthreads();
    if (tid < 64) {
        float bv = sv[tid]; int bix = si[tid];
        #pragma unroll
        for (int q2 = 1; q2 < 4; q2++) {
            float v = sv[q2 * 64 + tid]; int i = si[q2 * 64 + tid];
            if (v > bv || (v == bv && i < bix)) { bv = v; bix = i; }
        }
        g_word[tid] = bix;
        int m = g_mask[tid] | (bix == END_TOK);
        g_mask[tid] = m;
        sm[tid] = m;
    }
    __syncthreads();
    if (tid == 0) {
        int all = 1;
        for (int b2 = 0; b2 < 64; b2++) all &= sm[b2];
        if (all) g_done = 1;
    }
}

extern "C" void kernel_launch(void* const* d_in, const int* in_sizes, int n_in,
                              void* d_out, int out_size) {
    const float* feat = (const float*)d_in[0];
    const float* emb  = (const float*)d_in[1];
    const float* Wih  = (const float*)d_in[2];
    const float* Whh  = (const float*)d_in[3];
    const float* bih  = (const float*)d_in[4];
    const float* bhh  = (const float*)d_in[5];
    const float* Wl   = (const float*)d_in[6];
    const float* bl   = (const float*)d_in[7];
    float* out = (float*)d_out;

    kTransL<<<dim3(1000, 16), dim3(32, 8)>>>(Wl);
    kTransG<<<dim3(64, 32), dim3(32, 8)>>>(Wih, Whh);
    kInit<<<128, 256>>>(feat);
    for (int t = 0; t < TT; t++) {
        kGates<<<dim3(8, 16), 256>>>(emb);
        kPoint<<<64, 512>>>(bih, bhh);
        kB<<<125, 256>>>(bl, out, t);
        kC<<<1, 256>>>();
    }
}